// round 1
// baseline (speedup 1.0000x reference)
#include <cuda_runtime.h>
#include <math.h>

#define N_NODES 1024
#define E_EDGES 32768
#define EE_PAIRS 262144
#define CS 384
#define CZ 128
#define CG 16
#define NH 4
#define NR 64

// ---------------- scratch (static device globals; no runtime allocation) ----
__device__ float d_nl[N_NODES * CG];
__device__ float d_nr[N_NODES * CG];
__device__ float d_B[N_NODES * CG * CZ];      // 8 MB: B[n,i,c] = sum_j nr[n,j] * W_bg[i*16+j, c]
__device__ float d_q[E_EDGES * CZ];
__device__ float d_k[E_EDGES * CZ];
__device__ float d_v[E_EDGES * CZ];
__device__ float d_og[E_EDGES * CZ];
__device__ float d_attn[EE_PAIRS * NH];
__device__ float d_gupd[E_EDGES * CZ];
__device__ int   d_cnt[E_EDGES];
__device__ int   d_cur[E_EDGES];
__device__ int   d_off[E_EDGES + 1];
__device__ int   d_perm[EE_PAIRS];

// ---------------- K0: zero counters --------------------------------------
__global__ void k_zero() {
    int i = blockIdx.x * blockDim.x + threadIdx.x;
    for (; i < E_EDGES; i += gridDim.x * blockDim.x) {
        d_cnt[i] = 0;
        d_cur[i] = 0;
    }
}

// ---------------- K1: nl / nr node projections ----------------------------
__global__ void k_nlr(const float* __restrict__ nf,
                      const float* __restrict__ Wnl, const float* __restrict__ bnl,
                      const float* __restrict__ Wnr, const float* __restrict__ bnr) {
    __shared__ float s_nf[CS];
    int n = blockIdx.x;
    for (int i = threadIdx.x; i < CS; i += blockDim.x) s_nf[i] = nf[n * CS + i];
    __syncthreads();
    int t = threadIdx.x;
    if (t < CG) {
        float a = bnl[t];
        for (int k = 0; k < CS; k++) a += s_nf[k] * Wnl[k * CG + t];
        d_nl[n * CG + t] = a;
    } else if (t < 2 * CG) {
        int c = t - CG;
        float a = bnr[c];
        for (int k = 0; k < CS; k++) a += s_nf[k] * Wnr[k * CG + c];
        d_nr[n * CG + c] = a;
    }
}

// ---------------- K2: B[n,i,c] precompute ---------------------------------
__global__ void k_B(const float* __restrict__ Wbg) {
    __shared__ float s_nr[CG];
    int n = blockIdx.x;
    if (threadIdx.x < CG) s_nr[threadIdx.x] = d_nr[n * CG + threadIdx.x];
    __syncthreads();
    int c = threadIdx.x;  // 0..127
#pragma unroll
    for (int i = 0; i < CG; i++) {
        float a = 0.f;
#pragma unroll
        for (int j = 0; j < CG; j++) a += s_nr[j] * Wbg[(i * CG + j) * CZ + c];
        d_B[(n * CG + i) * CZ + c] = a;
    }
}

// ---------------- K3: fused layernorm + q/kv/og projections ---------------
// block: 256 threads handles 32 edges.  out cols 0..511 = [q(128) | kv(256) | og(128)]
__global__ __launch_bounds__(256) void k_proj(
    const float* __restrict__ ef, const float* __restrict__ lng, const float* __restrict__ lnb,
    const float* __restrict__ Wq, const float* __restrict__ bq,
    const float* __restrict__ Wkv, const float* __restrict__ bkv,
    const float* __restrict__ Wog, const float* __restrict__ bog) {
    __shared__ float s_ef[32][CZ];
    int e0 = blockIdx.x * 32;
    int warp = threadIdx.x >> 5, lane = threadIdx.x & 31;

    // layernorm: each warp normalizes 4 edges
    for (int r = 0; r < 4; r++) {
        int le = warp * 4 + r;
        int ge = e0 + le;
        float4 x = ((const float4*)(ef + (size_t)ge * CZ))[lane];
        float s = x.x + x.y + x.z + x.w;
        float ss = x.x * x.x + x.y * x.y + x.z * x.z + x.w * x.w;
#pragma unroll
        for (int o = 16; o > 0; o >>= 1) {
            s += __shfl_xor_sync(0xffffffffu, s, o);
            ss += __shfl_xor_sync(0xffffffffu, ss, o);
        }
        float m = s * (1.f / 128.f);
        float var = ss * (1.f / 128.f) - m * m;
        float inv = rsqrtf(var + 1e-5f);
        float4 g = ((const float4*)lng)[lane];
        float4 b = ((const float4*)lnb)[lane];
        float4 y;
        y.x = (x.x - m) * inv * g.x + b.x;
        y.y = (x.y - m) * inv * g.y + b.y;
        y.z = (x.z - m) * inv * g.z + b.z;
        y.w = (x.w - m) * inv * g.w + b.w;
        ((float4*)(&s_ef[le][0]))[lane] = y;
    }
    __syncthreads();

    int ct = threadIdx.x & 63;   // col thread (0..63)
    int et = threadIdx.x >> 6;   // edge thread (0..3)
    float acc[8][8];
#pragma unroll
    for (int i = 0; i < 8; i++)
#pragma unroll
        for (int j = 0; j < 8; j++) acc[i][j] = 0.f;

    for (int k = 0; k < CZ; k++) {
        float efr[8];
#pragma unroll
        for (int i = 0; i < 8; i++) efr[i] = s_ef[et + 4 * i][k];
        float wfr[8];
        wfr[0] = Wq[k * 128 + ct];
        wfr[1] = Wq[k * 128 + ct + 64];
        wfr[2] = Wkv[k * 256 + ct];
        wfr[3] = Wkv[k * 256 + ct + 64];
        wfr[4] = Wkv[k * 256 + ct + 128];
        wfr[5] = Wkv[k * 256 + ct + 192];
        wfr[6] = Wog[k * 128 + ct];
        wfr[7] = Wog[k * 128 + ct + 64];
#pragma unroll
        for (int i = 0; i < 8; i++)
#pragma unroll
            for (int j = 0; j < 8; j++) acc[i][j] += efr[i] * wfr[j];
    }

#pragma unroll
    for (int i = 0; i < 8; i++) {
        int ge = e0 + et + 4 * i;
        d_q[(size_t)ge * CZ + ct]        = acc[i][0] + bq[ct];
        d_q[(size_t)ge * CZ + ct + 64]   = acc[i][1] + bq[ct + 64];
        d_k[(size_t)ge * CZ + ct]        = acc[i][2] + bkv[ct];
        d_k[(size_t)ge * CZ + ct + 64]   = acc[i][3] + bkv[ct + 64];
        d_v[(size_t)ge * CZ + ct]        = acc[i][4] + bkv[ct + 128];
        d_v[(size_t)ge * CZ + ct + 64]   = acc[i][5] + bkv[ct + 192];
        float o1 = acc[i][6] + bog[ct];
        float o2 = acc[i][7] + bog[ct + 64];
        d_og[(size_t)ge * CZ + ct]      = 1.f / (1.f + expf(-o1));
        d_og[(size_t)ge * CZ + ct + 64] = 1.f / (1.f + expf(-o2));
    }
}

// ---------------- K4: per-pair bias + attention logits ---------------------
// one warp per pair; lane owns channels c = lane + 32*qq (head = qq)
__global__ __launch_bounds__(256) void k_pair(
    const int* __restrict__ eidx, const int* __restrict__ eeidx,
    const float* __restrict__ trans,
    const float* __restrict__ Wdb, const float* __restrict__ bdb,
    const float* __restrict__ bbg, const float* __restrict__ Wtb) {
    __shared__ float s_wdb[NR * CZ];   // 32 KB
    __shared__ float s_wtb[NH * CZ];   // transposed: [h][c]
    __shared__ float s_bdb[CZ];
    __shared__ float s_bbg[CZ];
    __shared__ float s_rbf[8][NR];

    for (int i = threadIdx.x; i < NR * CZ; i += 256) s_wdb[i] = Wdb[i];
    for (int i = threadIdx.x; i < NH * CZ; i += 256) {
        int c = i >> 2, h = i & 3;
        s_wtb[h * CZ + c] = Wtb[i];
    }
    if (threadIdx.x < CZ) {
        s_bdb[threadIdx.x] = bdb[threadIdx.x];
        s_bbg[threadIdx.x] = bbg[threadIdx.x];
    }
    __syncthreads();

    int warp = threadIdx.x >> 5, lane = threadIdx.x & 31;
    int gw = blockIdx.x * 8 + warp;
    int nwarps = gridDim.x * 8;
    const float SCALE = 0.088388347648318447f;  // 1/sqrt(128)
    const float SIG_INV = 3.2f;                 // 1/sigma, sigma = 20/64
    const float MU_STEP = 20.f / 63.f;

    for (int ee = gw; ee < EE_PAIRS; ee += nwarps) {
        int ee0 = eeidx[ee];
        int ee1 = eeidx[EE_PAIRS + ee];
        int n1 = eidx[ee1];
        int n2 = eidx[ee0];

        float nlv = (lane < CG) ? d_nl[n1 * CG + lane] : 0.f;

        float dx = trans[n1 * 3 + 0] - trans[n2 * 3 + 0] + 1e-8f;
        float dy = trans[n1 * 3 + 1] - trans[n2 * 3 + 1] + 1e-8f;
        float dz = trans[n1 * 3 + 2] - trans[n2 * 3 + 2] + 1e-8f;
        float dist = sqrtf(dx * dx + dy * dy + dz * dz);

        __syncwarp();
        {
            float t0 = (dist - MU_STEP * lane) * SIG_INV;
            float t1 = (dist - MU_STEP * (lane + 32)) * SIG_INV;
            s_rbf[warp][lane] = expf(-t0 * t0);
            s_rbf[warp][lane + 32] = expf(-t1 * t1);
        }
        __syncwarp();

        const float* Bn2 = d_B + (size_t)n2 * (CG * CZ);
        float gacc[4], dbacc[4];
#pragma unroll
        for (int qq = 0; qq < 4; qq++) {
            gacc[qq] = s_bbg[lane + 32 * qq];
            dbacc[qq] = s_bdb[lane + 32 * qq];
        }
#pragma unroll
        for (int i = 0; i < CG; i++) {
            float nli = __shfl_sync(0xffffffffu, nlv, i);
#pragma unroll
            for (int qq = 0; qq < 4; qq++)
                gacc[qq] += nli * Bn2[i * CZ + lane + 32 * qq];
        }
#pragma unroll 16
        for (int r = 0; r < NR; r++) {
            float rb = s_rbf[warp][r];
#pragma unroll
            for (int qq = 0; qq < 4; qq++)
                dbacc[qq] += rb * s_wdb[r * CZ + lane + 32 * qq];
        }

        float val[4] = {0.f, 0.f, 0.f, 0.f};
#pragma unroll
        for (int qq = 0; qq < 4; qq++) {
            int c = lane + 32 * qq;
            float tv = dbacc[qq] / (1.f + expf(-gacc[qq]));
#pragma unroll
            for (int h = 0; h < 4; h++) val[h] += tv * s_wtb[h * CZ + c];
            // q.k partial for head qq (c = qq*32 + lane)
            val[qq] += d_q[(size_t)ee1 * CZ + c] * d_k[(size_t)ee0 * CZ + c] * SCALE;
        }
#pragma unroll
        for (int h = 0; h < 4; h++)
#pragma unroll
            for (int o = 16; o > 0; o >>= 1)
                val[h] += __shfl_xor_sync(0xffffffffu, val[h], o);

        if (lane == 0) {
            float4 a = make_float4(val[0], val[1], val[2], val[3]);
            *(float4*)&d_attn[(size_t)ee * 4] = a;
            atomicAdd(&d_cnt[ee1], 1);
        }
    }
}

// ---------------- K5a: exclusive scan of counts (single block) -------------
__global__ __launch_bounds__(1024) void k_scan() {
    __shared__ int sd[1024];
    int t = threadIdx.x;
    int base = t * 32;
    int local[32];
    int s = 0;
#pragma unroll
    for (int j = 0; j < 32; j++) {
        local[j] = d_cnt[base + j];
        s += local[j];
    }
    sd[t] = s;
    __syncthreads();
    for (int o = 1; o < 1024; o <<= 1) {
        int v = (t >= o) ? sd[t - o] : 0;
        __syncthreads();
        sd[t] += v;
        __syncthreads();
    }
    int run = sd[t] - s;  // exclusive prefix
#pragma unroll
    for (int j = 0; j < 32; j++) {
        d_off[base + j] = run;
        run += local[j];
    }
    if (t == 1023) d_off[E_EDGES] = sd[1023];
}

// ---------------- K5b: scatter pair ids into CSR ---------------------------
__global__ void k_scatter(const int* __restrict__ eeidx) {
    int ee = blockIdx.x * blockDim.x + threadIdx.x;
    if (ee < EE_PAIRS) {
        int t = eeidx[EE_PAIRS + ee];
        int pos = atomicAdd(&d_cur[t], 1);
        d_perm[d_off[t] + pos] = ee;
    }
}

// ---------------- K6: segment softmax + weighted V aggregation + out gate --
__global__ __launch_bounds__(256) void k_soft(const int* __restrict__ eeidx) {
    int warp = threadIdx.x >> 5, lane = threadIdx.x & 31;
    int t = blockIdx.x * 8 + warp;
    if (t >= E_EDGES) return;
    int beg = d_off[t], end = d_off[t + 1];

    float mx0 = -1e30f, mx1 = -1e30f, mx2 = -1e30f, mx3 = -1e30f;
    for (int m = beg; m < end; m++) {
        int ee = d_perm[m];
        float4 a = *(const float4*)&d_attn[(size_t)ee * 4];
        mx0 = fmaxf(mx0, a.x); mx1 = fmaxf(mx1, a.y);
        mx2 = fmaxf(mx2, a.z); mx3 = fmaxf(mx3, a.w);
    }
    float sum0 = 0.f, sum1 = 0.f, sum2 = 0.f, sum3 = 0.f;
    float acc0 = 0.f, acc1 = 0.f, acc2 = 0.f, acc3 = 0.f;
    for (int m = beg; m < end; m++) {
        int ee = d_perm[m];
        int s = eeidx[ee];  // source edge ee0
        float4 a = *(const float4*)&d_attn[(size_t)ee * 4];
        float p0 = expf(a.x - mx0), p1 = expf(a.y - mx1);
        float p2 = expf(a.z - mx2), p3 = expf(a.w - mx3);
        sum0 += p0; sum1 += p1; sum2 += p2; sum3 += p3;
        const float* vp = d_v + (size_t)s * CZ;
        acc0 += p0 * vp[lane];
        acc1 += p1 * vp[lane + 32];
        acc2 += p2 * vp[lane + 64];
        acc3 += p3 * vp[lane + 96];
    }
    const float* ogp = d_og + (size_t)t * CZ;
    float* up = d_gupd + (size_t)t * CZ;
    up[lane]      = acc0 / (sum0 + 1e-16f) * ogp[lane];
    up[lane + 32] = acc1 / (sum1 + 1e-16f) * ogp[lane + 32];
    up[lane + 64] = acc2 / (sum2 + 1e-16f) * ogp[lane + 64];
    up[lane + 96] = acc3 / (sum3 + 1e-16f) * ogp[lane + 96];
}

// ---------------- K7: final output projection ------------------------------
__global__ __launch_bounds__(256) void k_out(const float* __restrict__ Wout,
                                             const float* __restrict__ bout,
                                             float* __restrict__ out) {
    __shared__ float s_u[32][CZ];
    int e0 = blockIdx.x * 32;
    for (int i = threadIdx.x; i < 32 * CZ; i += 256)
        ((float*)s_u)[i] = d_gupd[(size_t)e0 * CZ + i];
    __syncthreads();

    int ct = threadIdx.x & 31;
    int et = threadIdx.x >> 5;  // 0..7
    float acc[4][4];
#pragma unroll
    for (int i = 0; i < 4; i++)
#pragma unroll
        for (int j = 0; j < 4; j++) acc[i][j] = 0.f;

    for (int k = 0; k < CZ; k++) {
        float wf[4];
#pragma unroll
        for (int j = 0; j < 4; j++) wf[j] = Wout[k * CZ + ct + 32 * j];
#pragma unroll
        for (int i = 0; i < 4; i++) {
            float u = s_u[et + 8 * i][k];
#pragma unroll
            for (int j = 0; j < 4; j++) acc[i][j] += u * wf[j];
        }
    }
#pragma unroll
    for (int i = 0; i < 4; i++) {
        int ge = e0 + et + 8 * i;
#pragma unroll
        for (int j = 0; j < 4; j++)
            out[(size_t)ge * CZ + ct + 32 * j] = acc[i][j] + bout[ct + 32 * j];
    }
}

// ---------------- launch ----------------------------------------------------
extern "C" void kernel_launch(void* const* d_in, const int* in_sizes, int n_in,
                              void* d_out, int out_size) {
    const float* node_features = (const float*)d_in[0];
    const float* node_trans    = (const float*)d_in[1];
    const float* edge_features = (const float*)d_in[2];
    const int*   edge_index    = (const int*)d_in[3];
    const int*   ee_index      = (const int*)d_in[4];
    const float* ln_g  = (const float*)d_in[5];
    const float* ln_b  = (const float*)d_in[6];
    const float* W_nl  = (const float*)d_in[7];
    const float* b_nl  = (const float*)d_in[8];
    const float* W_nr  = (const float*)d_in[9];
    const float* b_nr  = (const float*)d_in[10];
    const float* W_bg  = (const float*)d_in[11];
    const float* b_bg  = (const float*)d_in[12];
    const float* W_db  = (const float*)d_in[13];
    const float* b_db  = (const float*)d_in[14];
    const float* W_tb  = (const float*)d_in[15];
    const float* W_q   = (const float*)d_in[16];
    const float* b_q   = (const float*)d_in[17];
    const float* W_kv  = (const float*)d_in[18];
    const float* b_kv  = (const float*)d_in[19];
    const float* W_og  = (const float*)d_in[20];
    const float* b_og  = (const float*)d_in[21];
    const float* W_out = (const float*)d_in[22];
    const float* b_out = (const float*)d_in[23];
    float* out = (float*)d_out;

    k_zero<<<64, 512>>>();
    k_nlr<<<N_NODES, 64>>>(node_features, W_nl, b_nl, W_nr, b_nr);
    k_B<<<N_NODES, 128>>>(W_bg);
    k_proj<<<E_EDGES / 32, 256>>>(edge_features, ln_g, ln_b,
                                  W_q, b_q, W_kv, b_kv, W_og, b_og);
    k_pair<<<2048, 256>>>(edge_index, ee_index, node_trans, W_db, b_db, b_bg, W_tb);
    k_scan<<<1, 1024>>>();
    k_scatter<<<EE_PAIRS / 256, 256>>>(ee_index);
    k_soft<<<E_EDGES / 8, 256>>>(ee_index);
    k_out<<<E_EDGES / 32, 256>>>(W_out, b_out, out);
}

// round 2
// speedup vs baseline: 1.2628x; 1.2628x over previous
#include <cuda_runtime.h>
#include <math.h>

#define N_NODES 1024
#define E_EDGES 32768
#define EE_PAIRS 262144
#define CS 384
#define CZ 128
#define CG 16
#define NH 4
#define NR 64

// ---------------- scratch ---------------------------------------------------
__device__ float d_nl[N_NODES * CG];
__device__ float d_nr[N_NODES * CG];
__device__ float d_q[E_EDGES * CZ];
__device__ float d_k[E_EDGES * CZ];
__device__ float d_v[E_EDGES * CZ];
__device__ float d_og[E_EDGES * CZ];
__device__ float d_attn[EE_PAIRS * NH];
__device__ float d_gupd[E_EDGES * CZ];
__device__ int   d_cnt[E_EDGES];
__device__ int   d_cur[E_EDGES];
__device__ int   d_off[E_EDGES + 1];
__device__ int   d_perm[EE_PAIRS];
__device__ int   d_cnt2[N_NODES];
__device__ int   d_cur2[N_NODES];
__device__ int   d_off2[N_NODES + 1];
__device__ int   d_perm2[EE_PAIRS];

// ---------------- K0: zero counters -----------------------------------------
__global__ void k_init() {
    int i = blockIdx.x * blockDim.x + threadIdx.x;
    for (; i < E_EDGES; i += gridDim.x * blockDim.x) {
        d_cnt[i] = 0;
        d_cur[i] = 0;
        if (i < N_NODES) { d_cnt2[i] = 0; d_cur2[i] = 0; }
    }
}

// ---------------- K1: count members per target edge & per n2 node -----------
__global__ void k_cnt(const int* __restrict__ eidx, const int* __restrict__ eeidx) {
    int ee = blockIdx.x * blockDim.x + threadIdx.x;
    if (ee < EE_PAIRS) {
        int ee0 = eeidx[ee];
        int ee1 = eeidx[EE_PAIRS + ee];
        atomicAdd(&d_cnt[ee1], 1);
        atomicAdd(&d_cnt2[eidx[ee0]], 1);
    }
}

// ---------------- K2a: exclusive scan (32768, single block) -----------------
__global__ __launch_bounds__(1024) void k_scan() {
    __shared__ int sd[1024];
    int t = threadIdx.x;
    int base = t * 32;
    int local[32];
    int s = 0;
#pragma unroll
    for (int j = 0; j < 32; j++) { local[j] = d_cnt[base + j]; s += local[j]; }
    sd[t] = s;
    __syncthreads();
    for (int o = 1; o < 1024; o <<= 1) {
        int v = (t >= o) ? sd[t - o] : 0;
        __syncthreads();
        sd[t] += v;
        __syncthreads();
    }
    int run = sd[t] - s;
#pragma unroll
    for (int j = 0; j < 32; j++) { d_off[base + j] = run; run += local[j]; }
    if (t == 1023) d_off[E_EDGES] = sd[1023];
}

// ---------------- K2b: exclusive scan (1024) ---------------------------------
__global__ __launch_bounds__(1024) void k_scan2() {
    __shared__ int sd[1024];
    int t = threadIdx.x;
    int v = d_cnt2[t];
    sd[t] = v;
    __syncthreads();
    for (int o = 1; o < 1024; o <<= 1) {
        int x = (t >= o) ? sd[t - o] : 0;
        __syncthreads();
        sd[t] += x;
        __syncthreads();
    }
    d_off2[t] = sd[t] - v;
    if (t == 1023) d_off2[N_NODES] = sd[1023];
}

// ---------------- K3: scatter into both CSRs ---------------------------------
__global__ void k_scatter(const int* __restrict__ eidx, const int* __restrict__ eeidx) {
    int ee = blockIdx.x * blockDim.x + threadIdx.x;
    if (ee < EE_PAIRS) {
        int ee0 = eeidx[ee];
        int ee1 = eeidx[EE_PAIRS + ee];
        int p = atomicAdd(&d_cur[ee1], 1);
        d_perm[d_off[ee1] + p] = ee;
        int n2 = eidx[ee0];
        int p2 = atomicAdd(&d_cur2[n2], 1);
        d_perm2[d_off2[n2] + p2] = ee;
    }
}

// ---------------- K4: nl / nr node projections -------------------------------
__global__ void k_nlr(const float* __restrict__ nf,
                      const float* __restrict__ Wnl, const float* __restrict__ bnl,
                      const float* __restrict__ Wnr, const float* __restrict__ bnr) {
    __shared__ float s_nf[CS];
    int n = blockIdx.x;
    for (int i = threadIdx.x; i < CS; i += blockDim.x) s_nf[i] = nf[n * CS + i];
    __syncthreads();
    int t = threadIdx.x;
    if (t < CG) {
        float a = bnl[t];
        for (int k = 0; k < CS; k++) a += s_nf[k] * Wnl[k * CG + t];
        d_nl[n * CG + t] = a;
    } else if (t < 2 * CG) {
        int c = t - CG;
        float a = bnr[c];
        for (int k = 0; k < CS; k++) a += s_nf[k] * Wnr[k * CG + c];
        d_nr[n * CG + c] = a;
    }
}

// ---------------- K5: fused layernorm + q/kv/og projections ------------------
// 256 threads, 32 edges/block. cols 0..511 = [q(128) | k(128) | v(128) | og(128)]
__global__ __launch_bounds__(256) void k_proj(
    const float* __restrict__ ef, const float* __restrict__ lng, const float* __restrict__ lnb,
    const float* __restrict__ Wq, const float* __restrict__ bq,
    const float* __restrict__ Wkv, const float* __restrict__ bkv,
    const float* __restrict__ Wog, const float* __restrict__ bog) {
    __shared__ float s_ef[32][CZ];      // 16 KB
    __shared__ float s_w[16][512];      // 32 KB weight k-tile
    int e0 = blockIdx.x * 32;
    int warp = threadIdx.x >> 5, lane = threadIdx.x & 31;

    // layernorm
    for (int r = 0; r < 4; r++) {
        int le = warp * 4 + r;
        int ge = e0 + le;
        float4 x = ((const float4*)(ef + (size_t)ge * CZ))[lane];
        float s = x.x + x.y + x.z + x.w;
        float ss = x.x * x.x + x.y * x.y + x.z * x.z + x.w * x.w;
#pragma unroll
        for (int o = 16; o > 0; o >>= 1) {
            s += __shfl_xor_sync(0xffffffffu, s, o);
            ss += __shfl_xor_sync(0xffffffffu, ss, o);
        }
        float m = s * (1.f / 128.f);
        float var = ss * (1.f / 128.f) - m * m;
        float inv = rsqrtf(var + 1e-5f);
        float4 g = ((const float4*)lng)[lane];
        float4 b = ((const float4*)lnb)[lane];
        float4 y;
        y.x = (x.x - m) * inv * g.x + b.x;
        y.y = (x.y - m) * inv * g.y + b.y;
        y.z = (x.z - m) * inv * g.z + b.z;
        y.w = (x.w - m) * inv * g.w + b.w;
        ((float4*)(&s_ef[le][0]))[lane] = y;
    }

    int ctg = threadIdx.x & 63;   // cols ctg*8 .. ctg*8+7
    int eh = threadIdx.x >> 6;    // edges eh*8 .. eh*8+7
    float acc[8][8];
#pragma unroll
    for (int i = 0; i < 8; i++)
#pragma unroll
        for (int j = 0; j < 8; j++) acc[i][j] = 0.f;

    for (int kt = 0; kt < 8; kt++) {
        __syncthreads();
        // cooperative weight tile load: rows kt*16 .. kt*16+15, 512 cols
#pragma unroll
        for (int j = 0; j < 8; j++) {
            int idx = threadIdx.x + j * 256;   // 0..2047 float4 units
            int kk = idx >> 7;
            int cg4 = (idx & 127) * 4;
            int k = kt * 16 + kk;
            float4 w;
            if (cg4 < 128)      w = *(const float4*)(Wq + k * 128 + cg4);
            else if (cg4 < 384) w = *(const float4*)(Wkv + k * 256 + (cg4 - 128));
            else                w = *(const float4*)(Wog + k * 128 + (cg4 - 384));
            *(float4*)&s_w[kk][cg4] = w;
        }
        __syncthreads();
#pragma unroll
        for (int kk = 0; kk < 16; kk += 4) {
            float4 ef4[8];
#pragma unroll
            for (int e = 0; e < 8; e++)
                ef4[e] = *(const float4*)&s_ef[eh * 8 + e][kt * 16 + kk];
#pragma unroll
            for (int dk = 0; dk < 4; dk++) {
                float4 wa = *(const float4*)&s_w[kk + dk][ctg * 8];
                float4 wb = *(const float4*)&s_w[kk + dk][ctg * 8 + 4];
#pragma unroll
                for (int e = 0; e < 8; e++) {
                    float efv = (dk == 0) ? ef4[e].x : (dk == 1) ? ef4[e].y
                               : (dk == 2) ? ef4[e].z : ef4[e].w;
                    acc[e][0] += efv * wa.x; acc[e][1] += efv * wa.y;
                    acc[e][2] += efv * wa.z; acc[e][3] += efv * wa.w;
                    acc[e][4] += efv * wb.x; acc[e][5] += efv * wb.y;
                    acc[e][6] += efv * wb.z; acc[e][7] += efv * wb.w;
                }
            }
        }
    }

    // epilogue
    int c0 = ctg * 8;
    float* dst;
    const float* bsrc;
    int lc;
    bool sig = false;
    if (c0 < 128)      { dst = d_q;  lc = c0;       bsrc = bq + lc; }
    else if (c0 < 256) { dst = d_k;  lc = c0 - 128; bsrc = bkv + lc; }
    else if (c0 < 384) { dst = d_v;  lc = c0 - 256; bsrc = bkv + 128 + lc; }
    else               { dst = d_og; lc = c0 - 384; bsrc = bog + lc; sig = true; }
    float bias[8];
#pragma unroll
    for (int j = 0; j < 8; j++) bias[j] = bsrc[j];
#pragma unroll
    for (int e = 0; e < 8; e++) {
        int ge = e0 + eh * 8 + e;
        float v[8];
#pragma unroll
        for (int j = 0; j < 8; j++) {
            v[j] = acc[e][j] + bias[j];
            if (sig) v[j] = 1.f / (1.f + __expf(-v[j]));
        }
        float4* o = (float4*)(dst + (size_t)ge * CZ + lc);
        o[0] = make_float4(v[0], v[1], v[2], v[3]);
        o[1] = make_float4(v[4], v[5], v[6], v[7]);
    }
}

// ---------------- K6: per-pair bias + attention logits (grouped by n2) -------
__global__ __launch_bounds__(256) void k_pair(
    const int* __restrict__ eidx, const int* __restrict__ eeidx,
    const float* __restrict__ trans,
    const float* __restrict__ Wdb, const float* __restrict__ bdb,
    const float* __restrict__ Wbg, const float* __restrict__ bbg,
    const float* __restrict__ Wtb) {
    __shared__ float s_wdbT[128][68];   // W_db transposed [c][r], padded
    __shared__ float s_BT[128][20];     // B[n2] transposed [c][i], padded
    __shared__ float s_wtb[4][128];
    __shared__ float s_bdb[128];
    __shared__ float s_bbg[128];
    __shared__ float s_nr[16];
    __shared__ float s_tr[3];

    int n2 = blockIdx.x;
    int t = threadIdx.x;

    for (int idx = t; idx < NR * CZ; idx += 256) {
        int r = idx >> 7, c = idx & 127;
        s_wdbT[c][r] = Wdb[idx];
    }
    for (int i = t; i < NH * CZ; i += 256) s_wtb[i & 3][i >> 2] = Wtb[i];
    if (t < 128) { s_bdb[t] = bdb[t]; s_bbg[t] = bbg[t]; }
    if (t < 16) s_nr[t] = d_nr[n2 * CG + t];
    if (t < 3)  s_tr[t] = trans[n2 * 3 + t];
    __syncthreads();
    {   // B[n2] transposed: s_BT[c][i] = sum_j nr[j] * Wbg[(i*16+j)*128+c]
        int c = t & 127, half = t >> 7;
#pragma unroll
        for (int i = half * 8; i < half * 8 + 8; i++) {
            float a = 0.f;
#pragma unroll
            for (int j = 0; j < CG; j++) a += s_nr[j] * Wbg[(i * CG + j) * CZ + c];
            s_BT[c][i] = a;
        }
    }
    __syncthreads();

    int warp = t >> 5, lane = t & 31;
    float trx = s_tr[0], try_ = s_tr[1], trz = s_tr[2];
    int beg = d_off2[n2], end = d_off2[n2 + 1];
    const float SCALE = 0.088388347648318447f;  // 1/sqrt(128)
    const float MU_STEP = 20.f / 63.f;
    const float INV_MU = 63.f / 20.f;
    const float SIG_INV = 3.2f;                 // 1/sigma, sigma = 20/64

    for (int m = beg + warp; m < end; m += 8) {
        int ee = d_perm2[m];
        int ee0 = eeidx[ee];
        int ee1 = eeidx[EE_PAIRS + ee];
        int n1 = eidx[ee1];

        float nlv = d_nl[n1 * CG + (lane & 15)];
        float nlr[16];
#pragma unroll
        for (int i = 0; i < 16; i++) nlr[i] = __shfl_sync(0xffffffffu, nlv, i);

        float dx = trans[n1 * 3 + 0] - trx + 1e-8f;
        float dy = trans[n1 * 3 + 1] - try_ + 1e-8f;
        float dz = trans[n1 * 3 + 2] - trz + 1e-8f;
        float dist = sqrtf(dx * dx + dy * dy + dz * dz);

        // 16-term rbf window around nearest mu (dropped terms < e^-66)
        int rc = (int)(dist * INV_MU + 0.5f);
        int lo = rc - 7;
        lo = lo < 0 ? 0 : lo;
        lo = lo > 48 ? 48 : lo;
        lo &= ~3;
        float rbf[16];
#pragma unroll
        for (int rr = 0; rr < 16; rr++) {
            float tt = (dist - (float)(lo + rr) * MU_STEP) * SIG_INV;
            rbf[rr] = __expf(-tt * tt);
        }

        float val[4] = {0.f, 0.f, 0.f, 0.f};
#pragma unroll
        for (int qq = 0; qq < 4; qq++) {
            int c = lane + 32 * qq;
            const float4* bp = (const float4*)&s_BT[c][0];
            float4 b0 = bp[0], b1 = bp[1], b2 = bp[2], b3 = bp[3];
            float g = s_bbg[c]
                + nlr[0] * b0.x + nlr[1] * b0.y + nlr[2] * b0.z + nlr[3] * b0.w
                + nlr[4] * b1.x + nlr[5] * b1.y + nlr[6] * b1.z + nlr[7] * b1.w
                + nlr[8] * b2.x + nlr[9] * b2.y + nlr[10] * b2.z + nlr[11] * b2.w
                + nlr[12] * b3.x + nlr[13] * b3.y + nlr[14] * b3.z + nlr[15] * b3.w;
            const float4* wp = (const float4*)&s_wdbT[c][lo];
            float4 w0 = wp[0], w1 = wp[1], w2 = wp[2], w3 = wp[3];
            float db = s_bdb[c]
                + rbf[0] * w0.x + rbf[1] * w0.y + rbf[2] * w0.z + rbf[3] * w0.w
                + rbf[4] * w1.x + rbf[5] * w1.y + rbf[6] * w1.z + rbf[7] * w1.w
                + rbf[8] * w2.x + rbf[9] * w2.y + rbf[10] * w2.z + rbf[11] * w2.w
                + rbf[12] * w3.x + rbf[13] * w3.y + rbf[14] * w3.z + rbf[15] * w3.w;
            float tv = db / (1.f + __expf(-g));
#pragma unroll
            for (int h = 0; h < 4; h++) val[h] += tv * s_wtb[h][c];
            val[qq] += d_q[(size_t)ee1 * CZ + c] * d_k[(size_t)ee0 * CZ + c] * SCALE;
        }
#pragma unroll
        for (int h = 0; h < 4; h++)
#pragma unroll
            for (int o = 16; o > 0; o >>= 1)
                val[h] += __shfl_xor_sync(0xffffffffu, val[h], o);
        if (lane == 0)
            *(float4*)&d_attn[(size_t)ee * 4] = make_float4(val[0], val[1], val[2], val[3]);
    }
}

// ---------------- K7: segment softmax + V aggregation + out gate -------------
__global__ __launch_bounds__(256) void k_soft(const int* __restrict__ eeidx) {
    int warp = threadIdx.x >> 5, lane = threadIdx.x & 31;
    int t = blockIdx.x * 8 + warp;
    if (t >= E_EDGES) return;
    int beg = d_off[t], end = d_off[t + 1];

    float mx0 = -1e30f, mx1 = -1e30f, mx2 = -1e30f, mx3 = -1e30f;
    for (int m = beg; m < end; m++) {
        int ee = d_perm[m];
        float4 a = *(const float4*)&d_attn[(size_t)ee * 4];
        mx0 = fmaxf(mx0, a.x); mx1 = fmaxf(mx1, a.y);
        mx2 = fmaxf(mx2, a.z); mx3 = fmaxf(mx3, a.w);
    }
    float sum0 = 0.f, sum1 = 0.f, sum2 = 0.f, sum3 = 0.f;
    float acc0 = 0.f, acc1 = 0.f, acc2 = 0.f, acc3 = 0.f;
    for (int m = beg; m < end; m++) {
        int ee = d_perm[m];
        int s = eeidx[ee];
        float4 a = *(const float4*)&d_attn[(size_t)ee * 4];
        float p0 = __expf(a.x - mx0), p1 = __expf(a.y - mx1);
        float p2 = __expf(a.z - mx2), p3 = __expf(a.w - mx3);
        sum0 += p0; sum1 += p1; sum2 += p2; sum3 += p3;
        const float* vp = d_v + (size_t)s * CZ;
        acc0 += p0 * vp[lane];
        acc1 += p1 * vp[lane + 32];
        acc2 += p2 * vp[lane + 64];
        acc3 += p3 * vp[lane + 96];
    }
    const float* ogp = d_og + (size_t)t * CZ;
    float* up = d_gupd + (size_t)t * CZ;
    up[lane]      = acc0 / (sum0 + 1e-16f) * ogp[lane];
    up[lane + 32] = acc1 / (sum1 + 1e-16f) * ogp[lane + 32];
    up[lane + 64] = acc2 / (sum2 + 1e-16f) * ogp[lane + 64];
    up[lane + 96] = acc3 / (sum3 + 1e-16f) * ogp[lane + 96];
}

// ---------------- K8: final output projection ---------------------------------
__global__ __launch_bounds__(256) void k_out(const float* __restrict__ Wout,
                                             const float* __restrict__ bout,
                                             float* __restrict__ out) {
    __shared__ float s_u[32][CZ];
    __shared__ float s_w[32][CZ];
    int e0 = blockIdx.x * 32;
#pragma unroll
    for (int j = 0; j < 4; j++) {
        int f = threadIdx.x + j * 256;   // float4 index 0..1023
        int row = f >> 5, c4 = (f & 31) * 4;
        *(float4*)&s_u[row][c4] = *(const float4*)(d_gupd + (size_t)(e0 + row) * CZ + c4);
    }

    int cg = threadIdx.x & 31;   // cols cg*4..+3
    int eh = threadIdx.x >> 5;   // edges eh*4..+3
    float acc[4][4];
#pragma unroll
    for (int i = 0; i < 4; i++)
#pragma unroll
        for (int j = 0; j < 4; j++) acc[i][j] = 0.f;

    for (int kt = 0; kt < 4; kt++) {
        __syncthreads();
#pragma unroll
        for (int j = 0; j < 4; j++) {
            int f = threadIdx.x + j * 256;
            int row = f >> 5, c4 = (f & 31) * 4;
            *(float4*)&s_w[row][c4] = *(const float4*)(Wout + (size_t)(kt * 32 + row) * CZ + c4);
        }
        __syncthreads();
#pragma unroll
        for (int kk = 0; kk < 32; kk += 4) {
            float4 ef4[4];
#pragma unroll
            for (int e = 0; e < 4; e++)
                ef4[e] = *(const float4*)&s_u[eh * 4 + e][kt * 32 + kk];
#pragma unroll
            for (int dk = 0; dk < 4; dk++) {
                float4 w = *(const float4*)&s_w[kk + dk][cg * 4];
#pragma unroll
                for (int e = 0; e < 4; e++) {
                    float u = (dk == 0) ? ef4[e].x : (dk == 1) ? ef4[e].y
                             : (dk == 2) ? ef4[e].z : ef4[e].w;
                    acc[e][0] += u * w.x; acc[e][1] += u * w.y;
                    acc[e][2] += u * w.z; acc[e][3] += u * w.w;
                }
            }
        }
    }
    float4 bo = *(const float4*)(bout + cg * 4);
#pragma unroll
    for (int e = 0; e < 4; e++) {
        int ge = e0 + eh * 4 + e;
        float4 r = make_float4(acc[e][0] + bo.x, acc[e][1] + bo.y,
                               acc[e][2] + bo.z, acc[e][3] + bo.w);
        *(float4*)(out + (size_t)ge * CZ + cg * 4) = r;
    }
}

// ---------------- launch ------------------------------------------------------
extern "C" void kernel_launch(void* const* d_in, const int* in_sizes, int n_in,
                              void* d_out, int out_size) {
    const float* node_features = (const float*)d_in[0];
    const float* node_trans    = (const float*)d_in[1];
    const float* edge_features = (const float*)d_in[2];
    const int*   edge_index    = (const int*)d_in[3];
    const int*   ee_index      = (const int*)d_in[4];
    const float* ln_g  = (const float*)d_in[5];
    const float* ln_b  = (const float*)d_in[6];
    const float* W_nl  = (const float*)d_in[7];
    const float* b_nl  = (const float*)d_in[8];
    const float* W_nr  = (const float*)d_in[9];
    const float* b_nr  = (const float*)d_in[10];
    const float* W_bg  = (const float*)d_in[11];
    const float* b_bg  = (const float*)d_in[12];
    const float* W_db  = (const float*)d_in[13];
    const float* b_db  = (const float*)d_in[14];
    const float* W_tb  = (const float*)d_in[15];
    const float* W_q   = (const float*)d_in[16];
    const float* b_q   = (const float*)d_in[17];
    const float* W_kv  = (const float*)d_in[18];
    const float* b_kv  = (const float*)d_in[19];
    const float* W_og  = (const float*)d_in[20];
    const float* b_og  = (const float*)d_in[21];
    const float* W_out = (const float*)d_in[22];
    const float* b_out = (const float*)d_in[23];
    float* out = (float*)d_out;

    k_init<<<64, 512>>>();
    k_cnt<<<EE_PAIRS / 256, 256>>>(edge_index, ee_index);
    k_scan<<<1, 1024>>>();
    k_scan2<<<1, 1024>>>();
    k_scatter<<<EE_PAIRS / 256, 256>>>(edge_index, ee_index);
    k_nlr<<<N_NODES, 64>>>(node_features, W_nl, b_nl, W_nr, b_nr);
    k_proj<<<E_EDGES / 32, 256>>>(edge_features, ln_g, ln_b,
                                  W_q, b_q, W_kv, b_kv, W_og, b_og);
    k_pair<<<N_NODES, 256>>>(edge_index, ee_index, node_trans,
                             W_db, b_db, W_bg, b_bg, W_tb);
    k_soft<<<E_EDGES / 8, 256>>>(ee_index);
    k_out<<<E_EDGES / 32, 256>>>(W_out, b_out, out);
}

// round 3
// speedup vs baseline: 1.5058x; 1.1924x over previous
#include <cuda_runtime.h>
#include <math.h>

typedef unsigned long long ull;

#define N_NODES 1024
#define E_EDGES 32768
#define EE_PAIRS 262144
#define CS 384
#define CZ 128
#define CG 16
#define NH 4
#define NR 64
#define LUT_N 8192
#define LUT_SCALE 256.0f

// ---------------- scratch ---------------------------------------------------
__device__ float d_nl[N_NODES * CG];
__device__ float d_nr[N_NODES * CG];
__device__ float d_q[E_EDGES * CZ];
__device__ float d_k[E_EDGES * CZ];
__device__ float d_v[E_EDGES * CZ];
__device__ float d_og[E_EDGES * CZ];
__device__ float d_attn[EE_PAIRS * NH];   // indexed by softmax-CSR slot
__device__ float d_gupd[E_EDGES * CZ];
__device__ float d_lut[LUT_N * CZ];       // dist_bias lookup table
__device__ int   d_cnt[E_EDGES];
__device__ int   d_cur[E_EDGES];
__device__ int   d_off[E_EDGES + 1];
__device__ int   d_cnt2[N_NODES];
__device__ int   d_cur2[N_NODES];
__device__ int   d_off2[N_NODES + 1];
__device__ int4  d_rec[EE_PAIRS];         // per n2-slot: {ee0, ee1, n1, softmax_slot}
__device__ int   d_src[EE_PAIRS];         // per softmax-slot: source edge ee0

// ---------------- f32x2 packed helpers ---------------------------------------
__device__ __forceinline__ ull pk2(float lo, float hi) {
    ull r;
    asm("mov.b64 %0, {%1, %2};" : "=l"(r) : "f"(lo), "f"(hi));
    return r;
}
__device__ __forceinline__ ull pkdup(float v) { return pk2(v, v); }
__device__ __forceinline__ void upk2(ull p, float& lo, float& hi) {
    asm("mov.b64 {%0, %1}, %2;" : "=f"(lo), "=f"(hi) : "l"(p));
}
__device__ __forceinline__ ull ffma2(ull a, ull b, ull c) {
    ull d;
    asm("fma.rn.f32x2 %0, %1, %2, %3;" : "=l"(d) : "l"(a), "l"(b), "l"(c));
    return d;
}

// ---------------- K0: zero counters -----------------------------------------
__global__ void k_init() {
    int i = blockIdx.x * blockDim.x + threadIdx.x;
    for (; i < E_EDGES; i += gridDim.x * blockDim.x) {
        d_cnt[i] = 0;
        d_cur[i] = 0;
        if (i < N_NODES) { d_cnt2[i] = 0; d_cur2[i] = 0; }
    }
}

// ---------------- K1: count members -----------------------------------------
__global__ void k_cnt(const int* __restrict__ eidx, const int* __restrict__ eeidx) {
    int ee = blockIdx.x * blockDim.x + threadIdx.x;
    if (ee < EE_PAIRS) {
        int e0 = eeidx[ee];
        int e1 = eeidx[EE_PAIRS + ee];
        atomicAdd(&d_cnt[e1], 1);
        atomicAdd(&d_cnt2[eidx[e0]], 1);
    }
}

// ---------------- K2a: exclusive scan (32768) --------------------------------
__global__ __launch_bounds__(1024) void k_scan() {
    __shared__ int sd[1024];
    int t = threadIdx.x;
    int base = t * 32;
    int local[32];
    int s = 0;
#pragma unroll
    for (int j = 0; j < 32; j++) { local[j] = d_cnt[base + j]; s += local[j]; }
    sd[t] = s;
    __syncthreads();
    for (int o = 1; o < 1024; o <<= 1) {
        int v = (t >= o) ? sd[t - o] : 0;
        __syncthreads();
        sd[t] += v;
        __syncthreads();
    }
    int run = sd[t] - s;
#pragma unroll
    for (int j = 0; j < 32; j++) { d_off[base + j] = run; run += local[j]; }
    if (t == 1023) d_off[E_EDGES] = sd[1023];
}

// ---------------- K2b: exclusive scan (1024) ----------------------------------
__global__ __launch_bounds__(1024) void k_scan2() {
    __shared__ int sd[1024];
    int t = threadIdx.x;
    int v = d_cnt2[t];
    sd[t] = v;
    __syncthreads();
    for (int o = 1; o < 1024; o <<= 1) {
        int x = (t >= o) ? sd[t - o] : 0;
        __syncthreads();
        sd[t] += x;
        __syncthreads();
    }
    d_off2[t] = sd[t] - v;
    if (t == 1023) d_off2[N_NODES] = sd[1023];
}

// ---------------- K3: nl / nr node projections --------------------------------
__global__ void k_nlr(const float* __restrict__ nf,
                      const float* __restrict__ Wnl, const float* __restrict__ bnl,
                      const float* __restrict__ Wnr, const float* __restrict__ bnr) {
    __shared__ float s_nf[CS];
    int n = blockIdx.x;
    for (int i = threadIdx.x; i < CS; i += blockDim.x) s_nf[i] = nf[n * CS + i];
    __syncthreads();
    int t = threadIdx.x;
    if (t < CG) {
        float a = bnl[t];
        for (int k = 0; k < CS; k++) a += s_nf[k] * Wnl[k * CG + t];
        d_nl[n * CG + t] = a;
    } else if (t < 2 * CG) {
        int c = t - CG;
        float a = bnr[c];
        for (int k = 0; k < CS; k++) a += s_nf[k] * Wnr[k * CG + c];
        d_nr[n * CG + c] = a;
    }
}

// ---------------- K4: fused layernorm + q/kv/og projections (f32x2) ----------
__global__ __launch_bounds__(256) void k_proj(
    const float* __restrict__ ef, const float* __restrict__ lng, const float* __restrict__ lnb,
    const float* __restrict__ Wq, const float* __restrict__ bq,
    const float* __restrict__ Wkv, const float* __restrict__ bkv,
    const float* __restrict__ Wog, const float* __restrict__ bog) {
    __shared__ float s_ef[32][CZ];      // 16 KB
    __shared__ float s_w[16][512];      // 32 KB
    int e0 = blockIdx.x * 32;
    int warp = threadIdx.x >> 5, lane = threadIdx.x & 31;

    for (int r = 0; r < 4; r++) {
        int le = warp * 4 + r;
        int ge = e0 + le;
        float4 x = ((const float4*)(ef + (size_t)ge * CZ))[lane];
        float s = x.x + x.y + x.z + x.w;
        float ss = x.x * x.x + x.y * x.y + x.z * x.z + x.w * x.w;
#pragma unroll
        for (int o = 16; o > 0; o >>= 1) {
            s += __shfl_xor_sync(0xffffffffu, s, o);
            ss += __shfl_xor_sync(0xffffffffu, ss, o);
        }
        float m = s * (1.f / 128.f);
        float var = ss * (1.f / 128.f) - m * m;
        float inv = rsqrtf(var + 1e-5f);
        float4 g = ((const float4*)lng)[lane];
        float4 b = ((const float4*)lnb)[lane];
        float4 y;
        y.x = (x.x - m) * inv * g.x + b.x;
        y.y = (x.y - m) * inv * g.y + b.y;
        y.z = (x.z - m) * inv * g.z + b.z;
        y.w = (x.w - m) * inv * g.w + b.w;
        ((float4*)(&s_ef[le][0]))[lane] = y;
    }

    int ctg = threadIdx.x & 63;   // cols ctg*8 .. +7
    int eh = threadIdx.x >> 6;    // edges eh*8 .. +7
    ull acc2[8][4];
#pragma unroll
    for (int i = 0; i < 8; i++)
#pragma unroll
        for (int j = 0; j < 4; j++) acc2[i][j] = pk2(0.f, 0.f);

    for (int kt = 0; kt < 8; kt++) {
        __syncthreads();
#pragma unroll
        for (int j = 0; j < 8; j++) {
            int idx = threadIdx.x + j * 256;
            int kk = idx >> 7;
            int cg4 = (idx & 127) * 4;
            int k = kt * 16 + kk;
            float4 w;
            if (cg4 < 128)      w = *(const float4*)(Wq + k * 128 + cg4);
            else if (cg4 < 384) w = *(const float4*)(Wkv + k * 256 + (cg4 - 128));
            else                w = *(const float4*)(Wog + k * 128 + (cg4 - 384));
            *(float4*)&s_w[kk][cg4] = w;
        }
        __syncthreads();
#pragma unroll
        for (int kk = 0; kk < 16; kk += 4) {
            float4 ef4[8];
#pragma unroll
            for (int e = 0; e < 8; e++)
                ef4[e] = *(const float4*)&s_ef[eh * 8 + e][kt * 16 + kk];
#pragma unroll
            for (int dk = 0; dk < 4; dk++) {
                ulonglong2 wA = *(const ulonglong2*)&s_w[kk + dk][ctg * 8];
                ulonglong2 wB = *(const ulonglong2*)&s_w[kk + dk][ctg * 8 + 4];
#pragma unroll
                for (int e = 0; e < 8; e++) {
                    float efv = (dk == 0) ? ef4[e].x : (dk == 1) ? ef4[e].y
                               : (dk == 2) ? ef4[e].z : ef4[e].w;
                    ull ed = pkdup(efv);
                    acc2[e][0] = ffma2(ed, wA.x, acc2[e][0]);
                    acc2[e][1] = ffma2(ed, wA.y, acc2[e][1]);
                    acc2[e][2] = ffma2(ed, wB.x, acc2[e][2]);
                    acc2[e][3] = ffma2(ed, wB.y, acc2[e][3]);
                }
            }
        }
    }

    int c0 = ctg * 8;
    float* dst;
    const float* bsrc;
    int lc;
    bool sig = false;
    if (c0 < 128)      { dst = d_q;  lc = c0;       bsrc = bq + lc; }
    else if (c0 < 256) { dst = d_k;  lc = c0 - 128; bsrc = bkv + lc; }
    else if (c0 < 384) { dst = d_v;  lc = c0 - 256; bsrc = bkv + 128 + lc; }
    else               { dst = d_og; lc = c0 - 384; bsrc = bog + lc; sig = true; }
    float bias[8];
#pragma unroll
    for (int j = 0; j < 8; j++) bias[j] = bsrc[j];
#pragma unroll
    for (int e = 0; e < 8; e++) {
        int ge = e0 + eh * 8 + e;
        float v[8];
        upk2(acc2[e][0], v[0], v[1]);
        upk2(acc2[e][1], v[2], v[3]);
        upk2(acc2[e][2], v[4], v[5]);
        upk2(acc2[e][3], v[6], v[7]);
#pragma unroll
        for (int j = 0; j < 8; j++) {
            v[j] += bias[j];
            if (sig) v[j] = 1.f / (1.f + __expf(-v[j]));
        }
        float4* o = (float4*)(dst + (size_t)ge * CZ + lc);
        o[0] = make_float4(v[0], v[1], v[2], v[3]);
        o[1] = make_float4(v[4], v[5], v[6], v[7]);
    }
}

// ---------------- K5: dist_bias LUT builder -----------------------------------
// grid 128 blocks x 128 threads; block handles 64 distance rows
__global__ __launch_bounds__(128) void k_lut(const float* __restrict__ Wdb,
                                             const float* __restrict__ bdb) {
    __shared__ float s_w[NR][CZ];   // 32 KB
    __shared__ float s_rbf[NR];
    int c = threadIdx.x;
    for (int i = c; i < NR * CZ; i += 128) ((float*)s_w)[i] = Wdb[i];
    float bd = bdb[c];
    __syncthreads();
    const float MU_STEP = 20.f / 63.f;
    const float SIG_INV = 3.2f;     // 1/sigma, sigma = 20/64
    for (int row = 0; row < 64; row++) {
        int dI = blockIdx.x * 64 + row;
        float dist = (float)dI * (1.0f / LUT_SCALE);
        if (c < NR) {
            float tt = (dist - (float)c * MU_STEP) * SIG_INV;
            s_rbf[c] = __expf(-tt * tt);
        }
        __syncthreads();
        float a = bd;
#pragma unroll 16
        for (int r = 0; r < NR; r++) a += s_rbf[r] * s_w[r][c];
        d_lut[dI * CZ + c] = a;
        __syncthreads();
    }
}

// ---------------- K6: scatter into CSRs ----------------------------------------
__global__ void k_scatter(const int* __restrict__ eidx, const int* __restrict__ eeidx) {
    int ee = blockIdx.x * blockDim.x + threadIdx.x;
    if (ee < EE_PAIRS) {
        int e0 = eeidx[ee];
        int e1 = eeidx[EE_PAIRS + ee];
        int p = atomicAdd(&d_cur[e1], 1);
        int slot = d_off[e1] + p;
        d_src[slot] = e0;
        int n2 = eidx[e0];
        int n1 = eidx[e1];
        int p2 = atomicAdd(&d_cur2[n2], 1);
        d_rec[d_off2[n2] + p2] = make_int4(e0, e1, n1, slot);
    }
}

// ---------------- K7: per-pair bias + attention logits ---------------------------
// one block per n2; lane owns channels c = lane*4 .. +3 (head = lane>>3)
__global__ __launch_bounds__(256) void k_pair(
    const float* __restrict__ trans,
    const float* __restrict__ Wbg, const float* __restrict__ bbg,
    const float* __restrict__ Wtb) {
    __shared__ float s_B[CG][CZ];   // 8 KB, row-major: conflict-free float4 on c
    __shared__ float s_nr[CG];
    int n2 = blockIdx.x, t = threadIdx.x;
    if (t < CG) s_nr[t] = d_nr[n2 * CG + t];
    __syncthreads();
    {
        int c = t & 127, half = t >> 7;
#pragma unroll
        for (int i = half * 8; i < half * 8 + 8; i++) {
            float a = 0.f;
#pragma unroll
            for (int j = 0; j < CG; j++) a += s_nr[j] * Wbg[(i * CG + j) * CZ + c];
            s_B[i][c] = a;
        }
    }
    __syncthreads();

    int warp = t >> 5, lane = t & 31;
    int c0 = lane * 4;
    ull bbg0 = *(const ull*)(bbg + c0);
    ull bbg1 = *(const ull*)(bbg + c0 + 2);
    float4 wtb0 = *(const float4*)(Wtb + (c0 + 0) * NH);
    float4 wtb1 = *(const float4*)(Wtb + (c0 + 1) * NH);
    float4 wtb2 = *(const float4*)(Wtb + (c0 + 2) * NH);
    float4 wtb3 = *(const float4*)(Wtb + (c0 + 3) * NH);
    float trx = trans[n2 * 3], try_ = trans[n2 * 3 + 1], trz = trans[n2 * 3 + 2];
    int beg = d_off2[n2], end = d_off2[n2 + 1];
    const float SCALE = 0.088388347648318447f;  // 1/sqrt(128)

    for (int m0 = beg + warp * 4; m0 < end; m0 += 32) {
        int np = end - m0; np = np > 4 ? 4 : np;
        int e0a[4], e1a[4], n1a[4], sla[4];
#pragma unroll
        for (int p = 0; p < 4; p++) {
            if (p < np) {
                int4 r = d_rec[m0 + p];
                e0a[p] = r.x; e1a[p] = r.y; n1a[p] = r.z; sla[p] = r.w;
            } else { e0a[p] = 0; e1a[p] = 0; n1a[p] = 0; sla[p] = 0; }
        }
        float nlv01 = d_nl[n1a[lane >> 4] * CG + (lane & 15)];
        float nlv23 = d_nl[n1a[2 + (lane >> 4)] * CG + (lane & 15)];

        ull g0[4], g1[4];
#pragma unroll
        for (int p = 0; p < 4; p++) { g0[p] = bbg0; g1[p] = bbg1; }
#pragma unroll
        for (int i = 0; i < CG; i++) {
            ull b0 = *(const ull*)&s_B[i][c0];
            ull b1 = *(const ull*)&s_B[i][c0 + 2];
#pragma unroll
            for (int p = 0; p < 4; p++) {
                float nli = __shfl_sync(0xffffffffu, (p < 2) ? nlv01 : nlv23,
                                        ((p & 1) << 4) | i);
                ull nd = pkdup(nli);
                g0[p] = ffma2(nd, b0, g0[p]);
                g1[p] = ffma2(nd, b1, g1[p]);
            }
        }

#pragma unroll
        for (int p = 0; p < 4; p++) {
            if (p >= np) break;   // np is warp-uniform
            int n1 = n1a[p], e0 = e0a[p], e1 = e1a[p];
            float dx = trans[n1 * 3] - trx + 1e-8f;
            float dy = trans[n1 * 3 + 1] - try_ + 1e-8f;
            float dz = trans[n1 * 3 + 2] - trz + 1e-8f;
            float dist = sqrtf(dx * dx + dy * dy + dz * dz);
            float u = dist * LUT_SCALE;
            int i0 = (int)u;
            i0 = i0 > (LUT_N - 2) ? (LUT_N - 2) : i0;
            float fr = u - (float)i0;
            float4 l0 = *(const float4*)(d_lut + (size_t)i0 * CZ + c0);
            float4 l1 = *(const float4*)(d_lut + (size_t)(i0 + 1) * CZ + c0);
            float db0 = l0.x + fr * (l1.x - l0.x);
            float db1 = l0.y + fr * (l1.y - l0.y);
            float db2 = l0.z + fr * (l1.z - l0.z);
            float db3 = l0.w + fr * (l1.w - l0.w);

            float ga, gb, gc, gd;
            upk2(g0[p], ga, gb);
            upk2(g1[p], gc, gd);
            float tv0 = __fdividef(db0, 1.f + __expf(-ga));
            float tv1 = __fdividef(db1, 1.f + __expf(-gb));
            float tv2 = __fdividef(db2, 1.f + __expf(-gc));
            float tv3 = __fdividef(db3, 1.f + __expf(-gd));

            float4 q4 = *(const float4*)(d_q + (size_t)e1 * CZ + c0);
            float4 k4 = *(const float4*)(d_k + (size_t)e0 * CZ + c0);
            float qk = q4.x * k4.x + q4.y * k4.y + q4.z * k4.z + q4.w * k4.w;

            float v0 = tv0 * wtb0.x + tv1 * wtb1.x + tv2 * wtb2.x + tv3 * wtb3.x;
            float v1 = tv0 * wtb0.y + tv1 * wtb1.y + tv2 * wtb2.y + tv3 * wtb3.y;
            float v2 = tv0 * wtb0.z + tv1 * wtb1.z + tv2 * wtb2.z + tv3 * wtb3.z;
            float v3 = tv0 * wtb0.w + tv1 * wtb1.w + tv2 * wtb2.w + tv3 * wtb3.w;
#pragma unroll
            for (int o = 16; o > 0; o >>= 1) {
                v0 += __shfl_xor_sync(0xffffffffu, v0, o);
                v1 += __shfl_xor_sync(0xffffffffu, v1, o);
                v2 += __shfl_xor_sync(0xffffffffu, v2, o);
                v3 += __shfl_xor_sync(0xffffffffu, v3, o);
            }
            float qs = qk;
            qs += __shfl_xor_sync(0xffffffffu, qs, 1);
            qs += __shfl_xor_sync(0xffffffffu, qs, 2);
            qs += __shfl_xor_sync(0xffffffffu, qs, 4);
            float q0 = __shfl_sync(0xffffffffu, qs, 0);
            float q1 = __shfl_sync(0xffffffffu, qs, 8);
            float q2 = __shfl_sync(0xffffffffu, qs, 16);
            float q3 = __shfl_sync(0xffffffffu, qs, 24);
            if (lane == 0)
                *(float4*)&d_attn[(size_t)sla[p] * 4] = make_float4(
                    v0 + SCALE * q0, v1 + SCALE * q1, v2 + SCALE * q2, v3 + SCALE * q3);
        }
    }
}

// ---------------- K8: segment softmax + V aggregation + out gate ----------------
__global__ __launch_bounds__(256) void k_soft() {
    int warp = threadIdx.x >> 5, lane = threadIdx.x & 31;
    int tgt = blockIdx.x * 8 + warp;
    if (tgt >= E_EDGES) return;
    int beg = d_off[tgt], end = d_off[tgt + 1];
    int hb = lane >> 3;
    int c0 = lane * 4;

    float mx = -1e30f;
    for (int m = beg; m < end; m++) mx = fmaxf(mx, d_attn[m * 4 + hb]);

    float sum = 0.f;
    float ax = 0.f, ay = 0.f, az = 0.f, aw = 0.f;
    for (int m = beg; m < end; m++) {
        float a = d_attn[m * 4 + hb];
        float pp = __expf(a - mx);
        sum += pp;
        int s = d_src[m];
        float4 v = *(const float4*)(d_v + (size_t)s * CZ + c0);
        ax += pp * v.x; ay += pp * v.y; az += pp * v.z; aw += pp * v.w;
    }
    float inv = 1.f / (sum + 1e-16f);
    float4 og = *(const float4*)(d_og + (size_t)tgt * CZ + c0);
    float4 r = make_float4(ax * inv * og.x, ay * inv * og.y,
                           az * inv * og.z, aw * inv * og.w);
    *(float4*)(d_gupd + (size_t)tgt * CZ + c0) = r;
}

// ---------------- K9: final output projection (f32x2) ----------------------------
__global__ __launch_bounds__(256) void k_out(const float* __restrict__ Wout,
                                             const float* __restrict__ bout,
                                             float* __restrict__ out) {
    __shared__ float s_u[32][CZ];
    __shared__ float s_w[32][CZ];
    int e0 = blockIdx.x * 32;
#pragma unroll
    for (int j = 0; j < 4; j++) {
        int f = threadIdx.x + j * 256;
        int row = f >> 5, c4 = (f & 31) * 4;
        *(float4*)&s_u[row][c4] = *(const float4*)(d_gupd + (size_t)(e0 + row) * CZ + c4);
    }

    int cg = threadIdx.x & 31;   // cols cg*4..+3
    int eh = threadIdx.x >> 5;   // edges eh*4..+3
    ull acc2[4][2];
#pragma unroll
    for (int i = 0; i < 4; i++) { acc2[i][0] = pk2(0.f, 0.f); acc2[i][1] = pk2(0.f, 0.f); }

    for (int kt = 0; kt < 4; kt++) {
        __syncthreads();
#pragma unroll
        for (int j = 0; j < 4; j++) {
            int f = threadIdx.x + j * 256;
            int row = f >> 5, c4 = (f & 31) * 4;
            *(float4*)&s_w[row][c4] = *(const float4*)(Wout + (size_t)(kt * 32 + row) * CZ + c4);
        }
        __syncthreads();
#pragma unroll
        for (int kk = 0; kk < 32; kk += 4) {
            float4 ef4[4];
#pragma unroll
            for (int e = 0; e < 4; e++)
                ef4[e] = *(const float4*)&s_u[eh * 4 + e][kt * 32 + kk];
#pragma unroll
            for (int dk = 0; dk < 4; dk++) {
                ulonglong2 w2 = *(const ulonglong2*)&s_w[kk + dk][cg * 4];
#pragma unroll
                for (int e = 0; e < 4; e++) {
                    float u = (dk == 0) ? ef4[e].x : (dk == 1) ? ef4[e].y
                             : (dk == 2) ? ef4[e].z : ef4[e].w;
                    ull ud = pkdup(u);
                    acc2[e][0] = ffma2(ud, w2.x, acc2[e][0]);
                    acc2[e][1] = ffma2(ud, w2.y, acc2[e][1]);
                }
            }
        }
    }
    float4 bo = *(const float4*)(bout + cg * 4);
#pragma unroll
    for (int e = 0; e < 4; e++) {
        int ge = e0 + eh * 4 + e;
        float r0, r1, r2, r3;
        upk2(acc2[e][0], r0, r1);
        upk2(acc2[e][1], r2, r3);
        *(float4*)(out + (size_t)ge * CZ + cg * 4) =
            make_float4(r0 + bo.x, r1 + bo.y, r2 + bo.z, r3 + bo.w);
    }
}

// ---------------- launch ----------------------------------------------------------
extern "C" void kernel_launch(void* const* d_in, const int* in_sizes, int n_in,
                              void* d_out, int out_size) {
    const float* node_features = (const float*)d_in[0];
    const float* node_trans    = (const float*)d_in[1];
    const float* edge_features = (const float*)d_in[2];
    const int*   edge_index    = (const int*)d_in[3];
    const int*   ee_index      = (const int*)d_in[4];
    const float* ln_g  = (const float*)d_in[5];
    const float* ln_b  = (const float*)d_in[6];
    const float* W_nl  = (const float*)d_in[7];
    const float* b_nl  = (const float*)d_in[8];
    const float* W_nr  = (const float*)d_in[9];
    const float* b_nr  = (const float*)d_in[10];
    const float* W_bg  = (const float*)d_in[11];
    const float* b_bg  = (const float*)d_in[12];
    const float* W_db  = (const float*)d_in[13];
    const float* b_db  = (const float*)d_in[14];
    const float* W_tb  = (const float*)d_in[15];
    const float* W_q   = (const float*)d_in[16];
    const float* b_q   = (const float*)d_in[17];
    const float* W_kv  = (const float*)d_in[18];
    const float* b_kv  = (const float*)d_in[19];
    const float* W_og  = (const float*)d_in[20];
    const float* b_og  = (const float*)d_in[21];
    const float* W_out = (const float*)d_in[22];
    const float* b_out = (const float*)d_in[23];
    float* out = (float*)d_out;

    k_init<<<64, 512>>>();                                           // 0
    k_cnt<<<EE_PAIRS / 256, 256>>>(edge_index, ee_index);            // 1
    k_scan<<<1, 1024>>>();                                           // 2
    k_scan2<<<1, 1024>>>();                                          // 3
    k_nlr<<<N_NODES, 64>>>(node_features, W_nl, b_nl, W_nr, b_nr);   // 4
    k_proj<<<E_EDGES / 32, 256>>>(edge_features, ln_g, ln_b,         // 5 (ncu slot)
                                  W_q, b_q, W_kv, b_kv, W_og, b_og);
    k_lut<<<128, 128>>>(W_db, b_db);                                 // 6
    k_scatter<<<EE_PAIRS / 256, 256>>>(edge_index, ee_index);        // 7
    k_pair<<<N_NODES, 256>>>(node_trans, W_bg, b_bg, W_tb);          // 8
    k_soft<<<E_EDGES / 8, 256>>>();                                  // 9
    k_out<<<E_EDGES / 32, 256>>>(W_out, b_out, out);                 // 10
}